// round 1
// baseline (speedup 1.0000x reference)
#include <cuda_runtime.h>
#include <math.h>

#define Bx 4
#define Lx 2048
#define Dx 512
#define Hx 8
#define DHx 64
#define BHx 32
#define KTOP 38
#define SCALEF 0.125f

// ---------------- scratch (device globals; no allocation allowed) ----------
__device__ float g_Q[BHx * Lx * DHx];      // 16 MB, [bh][l][d]
__device__ float g_K[BHx * Lx * DHx];      // 16 MB
__device__ float g_V[BHx * Lx * DHx];      // 16 MB
__device__ float g_M[BHx * Lx];            // sparsity measure per (bh, q)
__device__ int   g_top[BHx * KTOP];
__device__ float g_Ksum[BHx * DHx];
__device__ float g_Vmean[BHx * DHx];
__device__ float g_delta[BHx * KTOP * DHx];  // ctx_sparse - Vmean
__device__ float g_base[Bx * Dx];            // (cat Vmean) @ Wo + bo per batch

// ---------------------------------------------------------------------------
// Projection GEMM: Y = X[8192,512] @ W[512,512] + b, output in [bh][l][d] layout.
// BM=128, BN=128, BK=16, 256 threads, 8x8 micro-tile (strided by 16).
// ---------------------------------------------------------------------------
__global__ __launch_bounds__(256)
void proj_kernel(const float* __restrict__ X, const float* __restrict__ W,
                 const float* __restrict__ bias, float* __restrict__ out)
{
    __shared__ float As[16][132];  // [k][m], padded
    __shared__ float Bs[16][128];  // [k][n]

    const int tid = threadIdx.x;
    const int tx = tid & 15;
    const int ty = tid >> 4;
    const int mbase = blockIdx.y * 128;
    const int nbase = blockIdx.x * 128;

    float acc[8][8];
#pragma unroll
    for (int i = 0; i < 8; i++)
#pragma unroll
        for (int j = 0; j < 8; j++) acc[i][j] = 0.f;

    for (int kt = 0; kt < Dx; kt += 16) {
        // A tile: X[mbase..+128][kt..+16] -> As[k][m] (transposed store)
#pragma unroll
        for (int it = 0; it < 2; it++) {
            int lin = tid + it * 256;          // 0..511
            int m = lin >> 2;                  // 0..127
            int c4 = lin & 3;                  // 0..3
            float4 v = *reinterpret_cast<const float4*>(
                X + (size_t)(mbase + m) * Dx + kt + c4 * 4);
            As[c4 * 4 + 0][m] = v.x;
            As[c4 * 4 + 1][m] = v.y;
            As[c4 * 4 + 2][m] = v.z;
            As[c4 * 4 + 3][m] = v.w;
        }
        // B tile: W[kt..+16][nbase..+128] -> Bs[k][n]
#pragma unroll
        for (int it = 0; it < 2; it++) {
            int lin = tid + it * 256;
            int n4 = lin & 31;
            int k = lin >> 5;
            float4 v = *reinterpret_cast<const float4*>(
                W + (size_t)(kt + k) * Dx + nbase + n4 * 4);
            *reinterpret_cast<float4*>(&Bs[k][n4 * 4]) = v;
        }
        __syncthreads();
#pragma unroll
        for (int kk = 0; kk < 16; kk++) {
            float a[8], b[8];
#pragma unroll
            for (int i = 0; i < 8; i++) a[i] = As[kk][ty + 16 * i];
#pragma unroll
            for (int j = 0; j < 8; j++) b[j] = Bs[kk][tx + 16 * j];
#pragma unroll
            for (int i = 0; i < 8; i++)
#pragma unroll
                for (int j = 0; j < 8; j++) acc[i][j] += a[i] * b[j];
        }
        __syncthreads();
    }

    // epilogue: row r = b*L + l ; col c = h*64 + d ; out[(b*H+h)][l][d]
#pragma unroll
    for (int i = 0; i < 8; i++) {
        int r = mbase + ty + 16 * i;
        int b = r >> 11;
        int l = r & 2047;
#pragma unroll
        for (int j = 0; j < 8; j++) {
            int c = nbase + tx + 16 * j;
            int h = c >> 6;
            int d = c & 63;
            out[(((size_t)(b * Hx + h)) * Lx + l) * DHx + d] = acc[i][j] + bias[c];
        }
    }
}

// ---------------------------------------------------------------------------
// K column-sum and V mean per bh
// ---------------------------------------------------------------------------
__global__ void meansum_kernel()
{
    int bh = blockIdx.x;
    int tid = threadIdx.x;
    int d = tid & 63, s = tid >> 6;  // 4 slices
    float ks = 0.f, vs = 0.f;
    for (int k = s; k < Lx; k += 4) {
        ks += g_K[((size_t)bh * Lx + k) * DHx + d];
        vs += g_V[((size_t)bh * Lx + k) * DHx + d];
    }
    __shared__ float red[2][256];
    red[0][tid] = ks;
    red[1][tid] = vs;
    __syncthreads();
    if (tid < 64) {
        float a = red[0][d] + red[0][d + 64] + red[0][d + 128] + red[0][d + 192];
        float b = red[1][d] + red[1][d + 64] + red[1][d + 128] + red[1][d + 192];
        g_Ksum[bh * DHx + d] = a;
        g_Vmean[bh * DHx + d] = b * (1.0f / Lx);
    }
}

// ---------------------------------------------------------------------------
// Row stats: M[bh][q] = SCALE * ( max_k Q·K[k]  -  Q·Ksum / L )
// Block = (bh, 128-row q tile). Streaming 128-wide K tiles, 8x8 micro max-GEMM.
// Dynamic smem: Qs[128][68] + Ks[128][68] = 69632 bytes.
// ---------------------------------------------------------------------------
__global__ __launch_bounds__(256)
void score_kernel()
{
    extern __shared__ float sm[];
    float* Qs = sm;               // 128 rows, stride 68
    float* Ks = sm + 128 * 68;

    const int bh = blockIdx.y;
    const int qbase = blockIdx.x * 128;
    const int tid = threadIdx.x;
    const int tx = tid & 15;
    const int ty = tid >> 4;

    const float* Qg = g_Q + ((size_t)bh * Lx + qbase) * DHx;
#pragma unroll
    for (int it = 0; it < 8; it++) {
        int lin = tid + it * 256;
        int c4 = lin & 15, r = lin >> 4;
        float4 v = *reinterpret_cast<const float4*>(Qg + r * 64 + c4 * 4);
        *reinterpret_cast<float4*>(Qs + r * 68 + c4 * 4) = v;
    }

    float rmax[8];
#pragma unroll
    for (int i = 0; i < 8; i++) rmax[i] = -1e30f;

    for (int kb = 0; kb < Lx; kb += 128) {
        __syncthreads();  // protect Ks (and Qs on first iter)
        const float* Kg = g_K + ((size_t)bh * Lx + kb) * DHx;
#pragma unroll
        for (int it = 0; it < 8; it++) {
            int lin = tid + it * 256;
            int c4 = lin & 15, r = lin >> 4;
            float4 v = *reinterpret_cast<const float4*>(Kg + r * 64 + c4 * 4);
            *reinterpret_cast<float4*>(Ks + r * 68 + c4 * 4) = v;
        }
        __syncthreads();

        float acc[8][8];
#pragma unroll
        for (int i = 0; i < 8; i++)
#pragma unroll
            for (int j = 0; j < 8; j++) acc[i][j] = 0.f;

#pragma unroll 8
        for (int d = 0; d < 64; d++) {
            float a[8], b[8];
#pragma unroll
            for (int i = 0; i < 8; i++) a[i] = Qs[(ty + 16 * i) * 68 + d];
#pragma unroll
            for (int j = 0; j < 8; j++) b[j] = Ks[(tx + 16 * j) * 68 + d];
#pragma unroll
            for (int i = 0; i < 8; i++)
#pragma unroll
                for (int j = 0; j < 8; j++) acc[i][j] += a[i] * b[j];
        }
#pragma unroll
        for (int i = 0; i < 8; i++) {
            float m = acc[i][0];
#pragma unroll
            for (int j = 1; j < 8; j++) m = fmaxf(m, acc[i][j]);
            rmax[i] = fmaxf(rmax[i], m);
        }
    }

    // reduce max across the 16 tx threads (same ty -> same half-warp)
#pragma unroll
    for (int i = 0; i < 8; i++) {
        float m = rmax[i];
        m = fmaxf(m, __shfl_xor_sync(0xffffffffu, m, 1));
        m = fmaxf(m, __shfl_xor_sync(0xffffffffu, m, 2));
        m = fmaxf(m, __shfl_xor_sync(0xffffffffu, m, 4));
        m = fmaxf(m, __shfl_xor_sync(0xffffffffu, m, 8));
        rmax[i] = m;
    }

    if (tx == 0) {
        const float* ks = g_Ksum + bh * DHx;
#pragma unroll
        for (int i = 0; i < 8; i++) {
            int q = ty + 16 * i;
            float dot = 0.f;
#pragma unroll 16
            for (int d = 0; d < 64; d++) dot += Qs[q * 68 + d] * ks[d];
            g_M[(size_t)bh * Lx + qbase + q] = SCALEF * (rmax[i] - dot * (1.0f / Lx));
        }
    }
}

// ---------------------------------------------------------------------------
// Top-38 selection per bh (iterative max with index tiebreak = lowest index)
// ---------------------------------------------------------------------------
__global__ void topk_kernel()
{
    int bh = blockIdx.x;
    int tid = threadIdx.x;
    __shared__ float vals[Lx];
    __shared__ float rv[256];
    __shared__ int ri[256];
    for (int i = tid; i < Lx; i += 256) vals[i] = g_M[(size_t)bh * Lx + i];
    __syncthreads();
    for (int it = 0; it < KTOP; it++) {
        float best = -1e30f;
        int bidx = 0;
        for (int i = tid; i < Lx; i += 256) {
            float v = vals[i];
            if (v > best) { best = v; bidx = i; }
        }
        rv[tid] = best;
        ri[tid] = bidx;
        __syncthreads();
        for (int s = 128; s > 0; s >>= 1) {
            if (tid < s) {
                if (rv[tid + s] > rv[tid] ||
                    (rv[tid + s] == rv[tid] && ri[tid + s] < ri[tid])) {
                    rv[tid] = rv[tid + s];
                    ri[tid] = ri[tid + s];
                }
            }
            __syncthreads();
        }
        if (tid == 0) {
            g_top[bh * KTOP + it] = ri[0];
            vals[ri[0]] = -1e30f;
        }
        __syncthreads();
    }
}

// ---------------------------------------------------------------------------
// Sparse attention for one (bh, i): softmax(Q_sel·K^T * SCALE) @ V, minus Vmean
// ---------------------------------------------------------------------------
__global__ void sparse_attn_kernel()
{
    const int bh = blockIdx.y;
    const int i = blockIdx.x;
    const int tid = threadIdx.x;
    const int q = g_top[bh * KTOP + i];

    __shared__ float sc[Lx];
    __shared__ float qrow[DHx];
    __shared__ float red[256];

    if (tid < 64) qrow[tid] = g_Q[((size_t)bh * Lx + q) * DHx + tid];
    __syncthreads();

    const int warp = tid >> 5, lane = tid & 31;
    const float q0 = qrow[lane], q1 = qrow[lane + 32];
    for (int k = warp; k < Lx; k += 8) {
        const float* kr = g_K + ((size_t)bh * Lx + k) * DHx;
        float p = kr[lane] * q0 + kr[lane + 32] * q1;
#pragma unroll
        for (int o = 16; o > 0; o >>= 1) p += __shfl_xor_sync(0xffffffffu, p, o);
        if (lane == 0) sc[k] = p * SCALEF;
    }
    __syncthreads();

    float mx = -1e30f;
    for (int k = tid; k < Lx; k += 256) mx = fmaxf(mx, sc[k]);
    red[tid] = mx;
    __syncthreads();
    for (int s = 128; s > 0; s >>= 1) {
        if (tid < s) red[tid] = fmaxf(red[tid], red[tid + s]);
        __syncthreads();
    }
    mx = red[0];
    __syncthreads();

    float sum = 0.f;
    for (int k = tid; k < Lx; k += 256) {
        float e = __expf(sc[k] - mx);
        sc[k] = e;
        sum += e;
    }
    red[tid] = sum;
    __syncthreads();
    for (int s = 128; s > 0; s >>= 1) {
        if (tid < s) red[tid] += red[tid + s];
        __syncthreads();
    }
    float inv = 1.0f / red[0];
    __syncthreads();

    const int d = tid & 63, s4 = tid >> 6;
    float acc = 0.f;
    for (int k = s4; k < Lx; k += 4)
        acc += sc[k] * g_V[((size_t)bh * Lx + k) * DHx + d];
    red[tid] = acc;
    __syncthreads();
    if (tid < 64) {
        float c = (red[d] + red[d + 64] + red[d + 128] + red[d + 192]) * inv;
        g_delta[((size_t)bh * KTOP + i) * DHx + d] = c - g_Vmean[bh * DHx + d];
    }
}

// ---------------------------------------------------------------------------
// base[b] = (concat_h Vmean[b*H+h]) @ Wo + bo     (4 rows x 512 cols)
// ---------------------------------------------------------------------------
__global__ void base_kernel(const float* __restrict__ Wo, const float* __restrict__ bo)
{
    int b = blockIdx.x, j = threadIdx.x;
    float acc = bo[j];
    for (int c = 0; c < Dx; c++) {
        int h = c >> 6, d = c & 63;
        acc += g_Vmean[(b * Hx + h) * DHx + d] * Wo[(size_t)c * Dx + j];
    }
    g_base[b * Dx + j] = acc;
}

__global__ void fill_kernel(float* __restrict__ out)
{
    size_t idx = (size_t)blockIdx.x * blockDim.x + threadIdx.x;
    if (idx < (size_t)Bx * Lx * Dx) {
        int b = (int)(idx / ((size_t)Lx * Dx));
        int j = (int)(idx % Dx);
        out[idx] = g_base[b * Dx + j];
    }
}

// out[b, l_sel, :] += (ctx - Vmean) @ Wo[h*64:(h+1)*64, :]
__global__ void scatter_kernel(const float* __restrict__ Wo, float* __restrict__ out)
{
    const int bh = blockIdx.y;
    const int i = blockIdx.x;
    const int j = threadIdx.x;  // 512
    const int b = bh >> 3, h = bh & 7;
    const int l = g_top[bh * KTOP + i];
    __shared__ float dl[DHx];
    if (j < 64) dl[j] = g_delta[((size_t)bh * KTOP + i) * DHx + j];
    __syncthreads();
    float acc = 0.f;
#pragma unroll 16
    for (int d = 0; d < 64; d++) acc += dl[d] * Wo[(size_t)(h * 64 + d) * Dx + j];
    atomicAdd(&out[((size_t)b * Lx + l) * Dx + j], acc);
}

// ---------------------------------------------------------------------------
extern "C" void kernel_launch(void* const* d_in, const int* in_sizes, int n_in,
                              void* d_out, int out_size)
{
    const float* x  = (const float*)d_in[0];
    const float* Wq = (const float*)d_in[1];
    const float* bq = (const float*)d_in[2];
    const float* Wk = (const float*)d_in[3];
    const float* bk = (const float*)d_in[4];
    const float* Wv = (const float*)d_in[5];
    const float* bv = (const float*)d_in[6];
    const float* Wo = (const float*)d_in[7];
    const float* bo = (const float*)d_in[8];
    float* out = (float*)d_out;

    (void)in_sizes; (void)n_in; (void)out_size;

    // score_kernel needs 68 KB dynamic smem
    cudaFuncSetAttribute(score_kernel, cudaFuncAttributeMaxDynamicSharedMemorySize,
                         2 * 128 * 68 * (int)sizeof(float));

    float* gQ; cudaGetSymbolAddress((void**)&gQ, g_Q);
    float* gK; cudaGetSymbolAddress((void**)&gK, g_K);
    float* gV; cudaGetSymbolAddress((void**)&gV, g_V);

    dim3 pg(Dx / 128, (Bx * Lx) / 128);  // (4, 64)
    proj_kernel<<<pg, 256>>>(x, Wq, bq, gQ);
    proj_kernel<<<pg, 256>>>(x, Wk, bk, gK);
    proj_kernel<<<pg, 256>>>(x, Wv, bv, gV);

    meansum_kernel<<<BHx, 256>>>();

    score_kernel<<<dim3(Lx / 128, BHx), 256, 2 * 128 * 68 * sizeof(float)>>>();

    topk_kernel<<<BHx, 256>>>();

    sparse_attn_kernel<<<dim3(KTOP, BHx), 256>>>();

    base_kernel<<<Bx, Dx>>>(Wo, bo);
    fill_kernel<<<(Bx * Lx * Dx + 255) / 256, 256>>>(out);
    scatter_kernel<<<dim3(KTOP, BHx), Dx>>>(Wo, out);
}